// round 12
// baseline (speedup 1.0000x reference)
#include <cuda_runtime.h>
#include <cuda_bf16.h>
#include <cstdint>
#include <cstddef>

// Problem constants
#define BATCH 2
#define SEQ   2048
#define DMODEL 1024
#define NHEADS 16
#define HD    64
#define ROWS  (BATCH*SEQ)          // 4096
#define QKV_N (3*DMODEL)           // 3072
#define BH    (BATCH*NHEADS)       // 32
#define NKTILES (SEQ/64)           // 32
#define VTILE 5120                 // words per V tile (8 ks * 32 lanes * 20)

// Scratch (allocation-free rule: __device__ globals)
__device__ float    g_qs [(size_t)BH * SEQ * HD];       // Q*scale, fp32, head-major
__device__ uint32_t g_khl[(size_t)BH * SEQ * HD];       // K bf16 hi/lo pairs
__device__ float    g_v  [(size_t)BH * NKTILES * VTILE];// V tf32, fragment-swizzled
__device__ float    g_ctx[(size_t)ROWS * DMODEL];       // ctx, tf32-rounded
__device__ float    g_xr [(size_t)ROWS * DMODEL];       // tf32-rounded x
__device__ float    g_wqkvr[(size_t)DMODEL * QKV_N];    // tf32-rounded Wqkv
__device__ float    g_woutr[(size_t)DMODEL * DMODEL];   // tf32-rounded Wout

// ---------------------------------------------------------------------------
// helpers
// ---------------------------------------------------------------------------
__device__ __forceinline__ uint32_t f2tf(float x) {
    uint32_t r;
    asm("cvt.rna.tf32.f32 %0, %1;" : "=r"(r) : "f"(x));
    return r;
}

__device__ __forceinline__ void mma_tf32(float* c, const uint32_t* a, const uint32_t* b) {
    asm volatile(
        "mma.sync.aligned.m16n8k8.row.col.f32.tf32.tf32.f32 "
        "{%0,%1,%2,%3}, {%4,%5,%6,%7}, {%8,%9}, {%0,%1,%2,%3};"
        : "+f"(c[0]), "+f"(c[1]), "+f"(c[2]), "+f"(c[3])
        : "r"(a[0]), "r"(a[1]), "r"(a[2]), "r"(a[3]), "r"(b[0]), "r"(b[1]));
}

__device__ __forceinline__ void mma_bf16(float* c, const uint32_t* a, const uint32_t* b) {
    asm volatile(
        "mma.sync.aligned.m16n8k16.row.col.f32.bf16.bf16.f32 "
        "{%0,%1,%2,%3}, {%4,%5,%6,%7}, {%8,%9}, {%0,%1,%2,%3};"
        : "+f"(c[0]), "+f"(c[1]), "+f"(c[2]), "+f"(c[3])
        : "r"(a[0]), "r"(a[1]), "r"(a[2]), "r"(a[3]), "r"(b[0]), "r"(b[1]));
}

// split (x,y) fp32 pair -> bf16x2 hi word + bf16x2 lo word (lo = residual)
__device__ __forceinline__ void split_bf16x2(float x, float y, uint32_t& h, uint32_t& l) {
    __nv_bfloat16 xh = __float2bfloat16(x);
    __nv_bfloat16 yh = __float2bfloat16(y);
    __nv_bfloat162 hh = __halves2bfloat162(xh, yh);
    __nv_bfloat162 ll = __halves2bfloat162(
        __float2bfloat16(x - __bfloat162float(xh)),
        __float2bfloat16(y - __bfloat162float(yh)));
    h = *(uint32_t*)&hh;
    l = *(uint32_t*)&ll;
}

__device__ __forceinline__ void cpa16(void* smem, const void* gmem) {
    uint32_t sa = (uint32_t)__cvta_generic_to_shared(smem);
    asm volatile("cp.async.cg.shared.global [%0], [%1], 16;" :: "r"(sa), "l"(gmem));
}
#define CP_COMMIT() asm volatile("cp.async.commit_group;")
#define CP_WAIT1()  asm volatile("cp.async.wait_group 1;")
#define CP_WAIT2()  asm volatile("cp.async.wait_group 2;")

// ---------------------------------------------------------------------------
// prepass: round fp32 -> tf32-rounded fp32
// ---------------------------------------------------------------------------
__global__ void round_tf32_kernel(const float4* __restrict__ src,
                                  float4* __restrict__ dst, int n4)
{
    int i = blockIdx.x * blockDim.x + threadIdx.x;
    if (i < n4) {
        float4 v = src[i];
        v.x = __uint_as_float(f2tf(v.x));
        v.y = __uint_as_float(f2tf(v.y));
        v.z = __uint_as_float(f2tf(v.z));
        v.w = __uint_as_float(f2tf(v.w));
        dst[i] = v;
    }
}

// ---------------------------------------------------------------------------
// tf32 tensor-core GEMM, cp.async 4-stage ring, 1 sync per iteration.
// mode 0: C = A@B + bias.  mode 1: QKV scatter epilogue (head-major).
// BM=BN=128, BK=32, 256 threads = 8 warps (4Mx2N), warp tile 32x64.
// ---------------------------------------------------------------------------
#define GBM 128
#define GBN 128
#define GBK 32
#define ASTR 36
#define BSTR 136
#define GSTG (GBM*ASTR + GBK*BSTR)          // 8960 words per stage
#define GEMM_SMEM (4 * GSTG * 4)            // 143360 B

__global__ __launch_bounds__(256, 1) void gemm_tf32_async(
    int M, int N, int K,
    const float* __restrict__ A,
    const float* __restrict__ B,
    const float* __restrict__ bias,
    float* __restrict__ C,
    float* __restrict__ qs, uint32_t* __restrict__ khl, float* __restrict__ vv,
    int mode)
{
    extern __shared__ float gsm[];

    const int tid  = threadIdx.x;
    const int warp = tid >> 5;
    const int lane = tid & 31;
    const int grp  = lane >> 2;
    const int tig  = lane & 3;
    const int wm   = (warp >> 1) * 32;
    const int wn   = (warp & 1) * 64;
    const int bm   = blockIdx.y * GBM;
    const int bn   = blockIdx.x * GBN;

    const float* Abase = A + (size_t)bm * K;
    const float* Bbase = B + bn;

    float acc[2][8][4];
    #pragma unroll
    for (int mi = 0; mi < 2; mi++)
        #pragma unroll
        for (int ni = 0; ni < 8; ni++)
            #pragma unroll
            for (int r = 0; r < 4; r++) acc[mi][ni][r] = 0.f;

    auto loadStage = [&](int s, int k0) {
        float* Ab = gsm + s * GSTG;
        float* Bb = Ab + GBM * ASTR;
        #pragma unroll
        for (int u = 0; u < 4; u++) {
            int f = tid + u * 256;
            int r = f >> 3, k4 = (f & 7) * 4;
            cpa16(Ab + r * ASTR + k4, Abase + (size_t)r * K + k0 + k4);
        }
        #pragma unroll
        for (int u = 0; u < 4; u++) {
            int f = tid + u * 256;
            int r = f >> 5, c4 = (f & 31) * 4;
            cpa16(Bb + r * BSTR + c4, Bbase + (size_t)(k0 + r) * N + c4);
        }
    };

    const int nb = K / GBK;
    loadStage(0, 0); CP_COMMIT();
    loadStage(1, GBK); CP_COMMIT();
    loadStage(2, 2 * GBK); CP_COMMIT();

    for (int i = 0; i < nb; i++) {
        CP_WAIT2();          // group i complete (<=2 outstanding: i+1, i+2)
        __syncthreads();     // also: all warps done reading stage (i+3)&3 (iter i-1)
        if (i + 3 < nb) loadStage((i + 3) & 3, (i + 3) * GBK);
        CP_COMMIT();         // always commit: keeps group count uniform

        const float* Ab = gsm + (i & 3) * GSTG;
        const float* Bb = Ab + GBM * ASTR;

        #pragma unroll
        for (int ks = 0; ks < 4; ks++) {
            const int kb = ks * 8;
            uint32_t a[2][4], b[8][2];
            #pragma unroll
            for (int mi = 0; mi < 2; mi++) {
                int r0 = wm + mi * 16 + grp;
                a[mi][0] = __float_as_uint(Ab[(size_t)r0 * ASTR + kb + tig]);
                a[mi][1] = __float_as_uint(Ab[(size_t)(r0 + 8) * ASTR + kb + tig]);
                a[mi][2] = __float_as_uint(Ab[(size_t)r0 * ASTR + kb + tig + 4]);
                a[mi][3] = __float_as_uint(Ab[(size_t)(r0 + 8) * ASTR + kb + tig + 4]);
            }
            #pragma unroll
            for (int ni = 0; ni < 8; ni++) {
                int c0 = wn + ni * 8 + grp;
                b[ni][0] = __float_as_uint(Bb[(size_t)(kb + tig) * BSTR + c0]);
                b[ni][1] = __float_as_uint(Bb[(size_t)(kb + tig + 4) * BSTR + c0]);
            }
            #pragma unroll
            for (int mi = 0; mi < 2; mi++)
                #pragma unroll
                for (int ni = 0; ni < 8; ni++)
                    mma_tf32(acc[mi][ni], a[mi], b[ni]);
        }
    }

    if (mode == 0) {
        #pragma unroll
        for (int mi = 0; mi < 2; mi++) {
            #pragma unroll
            for (int ni = 0; ni < 8; ni++) {
                int row0 = bm + wm + mi * 16 + grp;
                int col  = bn + wn + ni * 8 + tig * 2;
                float2 bv = *(const float2*)(bias + col);
                float2 o0, o1;
                o0.x = acc[mi][ni][0] + bv.x;
                o0.y = acc[mi][ni][1] + bv.y;
                o1.x = acc[mi][ni][2] + bv.x;
                o1.y = acc[mi][ni][3] + bv.y;
                *(float2*)(C + (size_t)row0 * N + col)       = o0;
                *(float2*)(C + (size_t)(row0 + 8) * N + col) = o1;
            }
        }
    } else {
        // QKV scatter: Q scaled fp32 head-major; K bf16 hi/lo pairs head-major;
        // V tf32 in mma-fragment-swizzled tiles.
        auto scatter = [&](int row, int col, float va, float vb) {
            int b2 = row >> 11, s = row & 2047;
            int sec = col >> 10;
            int h = (col & 1023) >> 6, d = col & 63;
            if (sec == 0) {
                size_t base = ((size_t)((b2 << 4) + h) * SEQ + s) * HD + d;
                float2 o = { va * 0.125f, vb * 0.125f };
                *(float2*)(qs + base) = o;
            } else if (sec == 1) {
                size_t base = ((size_t)((b2 << 4) + h) * SEQ + s) * HD + d;
                uint2 o;
                split_bf16x2(va, vb, o.x, o.y);
                *(uint2*)(khl + base) = o;
            } else {
                int ktile = s >> 6, j = s & 63;
                int ksv = j >> 3, tigv = j & 3, rv = (j >> 2) & 1;
                size_t tbase = ((size_t)((b2 << 4) + h) * NKTILES + ktile) * VTILE;
                int g0 = d & 7, nt0 = d >> 3;
                int g1 = (d + 1) & 7, nt1 = (d + 1) >> 3;
                vv[tbase + (size_t)(ksv * 32 + 4 * g0 + tigv) * 20 + nt0 * 2 + rv] =
                    __uint_as_float(f2tf(va));
                vv[tbase + (size_t)(ksv * 32 + 4 * g1 + tigv) * 20 + nt1 * 2 + rv] =
                    __uint_as_float(f2tf(vb));
            }
        };
        #pragma unroll
        for (int mi = 0; mi < 2; mi++) {
            #pragma unroll
            for (int ni = 0; ni < 8; ni++) {
                int row0 = bm + wm + mi * 16 + grp;
                int col  = bn + wn + ni * 8 + tig * 2;
                float2 bv = *(const float2*)(bias + col);
                scatter(row0,     col, acc[mi][ni][0] + bv.x, acc[mi][ni][1] + bv.y);
                scatter(row0 + 8, col, acc[mi][ni][2] + bv.x, acc[mi][ni][3] + bv.y);
            }
        }
    }
}

// ---------------------------------------------------------------------------
// Tensor-core causal flash attention, cp.async 2-stage K/V pipeline.
// QK^T: 3xBF16 m16n8k16 (hi/lo split).  PV: 1xTF32, V pre-swizzled so each
// thread's B-fragments for one ks come from 4 LDS.128 (conflict-free, stride 20).
// Block = 128 q rows of one (b,h); 8 warps; 2 CTAs/SM.
// ---------------------------------------------------------------------------
#define BQ 128
#define BK 64
#define KROW 72     // uint32 words per K smem row (64 data + 8 pad)
#define PSTR 68
#define KTILE (BK*KROW)
#define ATTN_SMEM ((2*KTILE + 2*VTILE + BQ*PSTR) * 4)   // 112640 B

__global__ __launch_bounds__(256, 2) void attn_tc_kernel(
    const float* __restrict__ qs, const uint32_t* __restrict__ khl,
    const float* __restrict__ vsrc, float* __restrict__ ctx)
{
    extern __shared__ float sm[];
    uint32_t* KhlS = (uint32_t*)sm;         // [2][BK][KROW]
    float* VtS = sm + 2 * KTILE;            // [2][VTILE] fragment-swizzled
    float* Ps  = VtS + 2 * VTILE;           // [BQ][PSTR]

    const int qt = gridDim.x - 1 - blockIdx.x;   // heavy tiles first
    const int bh = blockIdx.y;
    const int b = bh >> 4;
    const int tid = threadIdx.x;
    const int w = tid >> 5, lane = tid & 31;
    const int grp = lane >> 2, tig = lane & 3;

    const uint32_t* kbase = khl + (size_t)bh * SEQ * HD;
    const float* vbase = vsrc + (size_t)bh * NKTILES * VTILE;

    auto load_tile = [&](int kt, int stage) {
        const uint32_t* ks = kbase + (size_t)(kt * BK) * HD;
        uint32_t* kd = KhlS + stage * KTILE;
        #pragma unroll
        for (int u = 0; u < 4; u++) {
            int f = tid + u * 256;
            int j = f >> 4, c = (f & 15) * 4;
            cpa16(kd + j * KROW + c, ks + (size_t)j * HD + c);
        }
        const float* vs = vbase + (size_t)kt * VTILE;
        float* vd = VtS + stage * VTILE;
        #pragma unroll
        for (int u = 0; u < 5; u++) {
            int f = (tid + u * 256) * 4;    // 1280 x 16B = 5120 words
            cpa16(vd + f, vs + f);
        }
    };

    const int nkt = 2 * qt + 2;

    load_tile(0, 0); CP_COMMIT();
    load_tile(1, 1); CP_COMMIT();

    const float* qsrc = qs + ((size_t)bh * SEQ + qt * BQ) * HD;
    #pragma unroll
    for (int u = 0; u < 8; u++) {
        int f = tid + u * 256;
        int r = f >> 4, c = (f & 15) * 4;
        *(float4*)(Ps + r * PSTR + c) = *(const float4*)(qsrc + (size_t)r * HD + c);
    }
    __syncthreads();

    const int r0 = w * 16 + grp, r1 = r0 + 8;

    // Q fragments: bf16 hi/lo split, m16n8k16 layout, register resident
    uint32_t qh[4][4], ql[4][4];
    #pragma unroll
    for (int ks = 0; ks < 4; ks++) {
        int kb = ks * 16 + 2 * tig;
        float2 x0 = *(const float2*)(Ps + r0 * PSTR + kb);
        float2 x1 = *(const float2*)(Ps + r1 * PSTR + kb);
        float2 x2 = *(const float2*)(Ps + r0 * PSTR + kb + 8);
        float2 x3 = *(const float2*)(Ps + r1 * PSTR + kb + 8);
        split_bf16x2(x0.x, x0.y, qh[ks][0], ql[ks][0]);
        split_bf16x2(x1.x, x1.y, qh[ks][1], ql[ks][1]);
        split_bf16x2(x2.x, x2.y, qh[ks][2], ql[ks][2]);
        split_bf16x2(x3.x, x3.y, qh[ks][3], ql[ks][3]);
    }

    float oacc[8][4];
    #pragma unroll
    for (int nt = 0; nt < 8; nt++)
        #pragma unroll
        for (int r = 0; r < 4; r++) oacc[nt][r] = 0.f;
    float m0 = -1e30f, m1 = -1e30f, l0 = 0.f, l1 = 0.f;

    int cur = 0;
    for (int kt = 0; kt < nkt; kt++) {
        CP_WAIT1();
        __syncthreads();

        const bool active = (kt * BK <= qt * BQ + w * 16 + 15);
        if (active) {
            const uint32_t* Khl = KhlS + cur * KTILE;
            const float* Vt = VtS + cur * VTILE;

            // --- QK^T (3xBF16, m16n8k16) ---
            float s[8][4];
            #pragma unroll
            for (int nt = 0; nt < 8; nt++)
                #pragma unroll
                for (int r = 0; r < 4; r++) s[nt][r] = 0.f;

            #pragma unroll
            for (int ks = 0; ks < 4; ks++) {
                #pragma unroll
                for (int nt = 0; nt < 8; nt++) {
                    int bi = (nt * 8 + grp) * KROW + (ks * 8 + tig) * 2;
                    uint2 w0 = *(const uint2*)&Khl[bi];
                    uint2 w1 = *(const uint2*)&Khl[bi + 8];
                    uint32_t bh2[2] = { w0.x, w1.x };
                    uint32_t bl2[2] = { w0.y, w1.y };
                    mma_bf16(s[nt], qh[ks], bh2);
                    mma_bf16(s[nt], qh[ks], bl2);
                    mma_bf16(s[nt], ql[ks], bh2);
                }
            }

            // --- causal mask (diagonal tiles only) ---
            const int q0 = qt * BQ + r0, q1 = qt * BQ + r1;
            if (kt * BK + BK - 1 > q0) {
                #pragma unroll
                for (int nt = 0; nt < 8; nt++) {
                    int jg = kt * BK + nt * 8 + 2 * tig;
                    if (jg     > q0) s[nt][0] = -1e30f;
                    if (jg + 1 > q0) s[nt][1] = -1e30f;
                    if (jg     > q1) s[nt][2] = -1e30f;
                    if (jg + 1 > q1) s[nt][3] = -1e30f;
                }
            }

            // --- online softmax ---
            float tm0 = -1e30f, tm1 = -1e30f;
            #pragma unroll
            for (int nt = 0; nt < 8; nt++) {
                tm0 = fmaxf(tm0, fmaxf(s[nt][0], s[nt][1]));
                tm1 = fmaxf(tm1, fmaxf(s[nt][2], s[nt][3]));
            }
            tm0 = fmaxf(tm0, __shfl_xor_sync(0xffffffffu, tm0, 1));
            tm0 = fmaxf(tm0, __shfl_xor_sync(0xffffffffu, tm0, 2));
            tm1 = fmaxf(tm1, __shfl_xor_sync(0xffffffffu, tm1, 1));
            tm1 = fmaxf(tm1, __shfl_xor_sync(0xffffffffu, tm1, 2));
            float nm0 = fmaxf(m0, tm0), nm1 = fmaxf(m1, tm1);
            float cr0 = __expf(m0 - nm0), cr1 = __expf(m1 - nm1);
            m0 = nm0; m1 = nm1;
            l0 *= cr0; l1 *= cr1;
            #pragma unroll
            for (int nt = 0; nt < 8; nt++) {
                oacc[nt][0] *= cr0; oacc[nt][1] *= cr0;
                oacc[nt][2] *= cr1; oacc[nt][3] *= cr1;
            }

            float ls0 = 0.f, ls1 = 0.f;
            #pragma unroll
            for (int nt = 0; nt < 8; nt++) {
                float p0 = __expf(s[nt][0] - m0);
                float p1 = __expf(s[nt][1] - m0);
                float p2 = __expf(s[nt][2] - m1);
                float p3 = __expf(s[nt][3] - m1);
                ls0 += p0 + p1; ls1 += p2 + p3;
                int cc = nt * 8 + 2 * tig;
                float2 w0, w1;
                w0.x = __uint_as_float(f2tf(p0)); w0.y = __uint_as_float(f2tf(p1));
                w1.x = __uint_as_float(f2tf(p2)); w1.y = __uint_as_float(f2tf(p3));
                *(float2*)(Ps + r0 * PSTR + cc) = w0;
                *(float2*)(Ps + r1 * PSTR + cc) = w1;
            }
            ls0 += __shfl_xor_sync(0xffffffffu, ls0, 1);
            ls0 += __shfl_xor_sync(0xffffffffu, ls0, 2);
            ls1 += __shfl_xor_sync(0xffffffffu, ls1, 1);
            ls1 += __shfl_xor_sync(0xffffffffu, ls1, 2);
            l0 += ls0; l1 += ls1;

            __syncwarp();   // P stores visible to same-warp fragment loads

            // --- PV (1xTF32, m16n8k8), V fragment-swizzled: 4x LDS.128 per ks ---
            #pragma unroll
            for (int ks = 0; ks < 8; ks++) {
                uint32_t a[4];
                int c0i = ks * 8 + tig;
                a[0] = __float_as_uint(Ps[r0 * PSTR + c0i]);
                a[1] = __float_as_uint(Ps[r1 * PSTR + c0i]);
                a[2] = __float_as_uint(Ps[r0 * PSTR + c0i + 4]);
                a[3] = __float_as_uint(Ps[r1 * PSTR + c0i + 4]);
                const float* vc = Vt + (ks * 32 + lane) * 20;
                float4 vq[4];                      // contiguous array (fixes R11 UB)
                vq[0] = *(const float4*)(vc);
                vq[1] = *(const float4*)(vc + 4);
                vq[2] = *(const float4*)(vc + 8);
                vq[3] = *(const float4*)(vc + 12);
                const float* vw = (const float*)vq;   // 16 contiguous floats
                #pragma unroll
                for (int nt = 0; nt < 8; nt++) {
                    uint32_t bb[2];
                    bb[0] = __float_as_uint(vw[nt * 2]);
                    bb[1] = __float_as_uint(vw[nt * 2 + 1]);
                    mma_tf32(oacc[nt], a, bb);
                }
            }
        }

        __syncthreads();
        if (kt + 2 < nkt) load_tile(kt + 2, cur);
        CP_COMMIT();
        cur ^= 1;
    }

    // --- epilogue: write tf32-rounded ctx (out-proj consumes it as A) ---
    float inv0 = 1.f / l0, inv1 = 1.f / l1;
    const int h = bh & 15;
    float* ob = ctx + (size_t)(b * SEQ + qt * BQ) * DMODEL + h * HD;
    #pragma unroll
    for (int nt = 0; nt < 8; nt++) {
        int cc = nt * 8 + 2 * tig;
        float2 o0, o1;
        o0.x = __uint_as_float(f2tf(oacc[nt][0] * inv0));
        o0.y = __uint_as_float(f2tf(oacc[nt][1] * inv0));
        o1.x = __uint_as_float(f2tf(oacc[nt][2] * inv1));
        o1.y = __uint_as_float(f2tf(oacc[nt][3] * inv1));
        *(float2*)(ob + (size_t)r0 * DMODEL + cc) = o0;
        *(float2*)(ob + (size_t)r1 * DMODEL + cc) = o1;
    }
}

// ---------------------------------------------------------------------------
extern "C" void kernel_launch(void* const* d_in, const int* in_sizes, int n_in,
                              void* d_out, int out_size)
{
    const float* x    = (const float*)d_in[0];
    const float* Wqkv = (const float*)d_in[1];
    const float* bqkv = (const float*)d_in[2];
    const float* Wout = (const float*)d_in[3];
    const float* bout = (const float*)d_in[4];
    float* out = (float*)d_out;

    float *qs, *vv, *ctx, *xr, *wqkvr, *woutr;
    uint32_t* khl;
    cudaGetSymbolAddress((void**)&qs, g_qs);
    cudaGetSymbolAddress((void**)&khl, g_khl);
    cudaGetSymbolAddress((void**)&vv, g_v);
    cudaGetSymbolAddress((void**)&ctx, g_ctx);
    cudaGetSymbolAddress((void**)&xr, g_xr);
    cudaGetSymbolAddress((void**)&wqkvr, g_wqkvr);
    cudaGetSymbolAddress((void**)&woutr, g_woutr);

    cudaFuncSetAttribute(gemm_tf32_async,
                         cudaFuncAttributeMaxDynamicSharedMemorySize, GEMM_SMEM);
    cudaFuncSetAttribute(attn_tc_kernel,
                         cudaFuncAttributeMaxDynamicSharedMemorySize, ATTN_SMEM);

    // 0) prepass: tf32-round GEMM inputs
    {
        int n4x = ROWS * DMODEL / 4;
        int n4w = DMODEL * QKV_N / 4;
        int n4o = DMODEL * DMODEL / 4;
        round_tf32_kernel<<<(n4x + 255) / 256, 256>>>((const float4*)x, (float4*)xr, n4x);
        round_tf32_kernel<<<(n4w + 255) / 256, 256>>>((const float4*)Wqkv, (float4*)wqkvr, n4w);
        round_tf32_kernel<<<(n4o + 255) / 256, 256>>>((const float4*)Wout, (float4*)woutr, n4o);
    }

    // 1) qkv projection with scatter epilogue -> qs / khl(bf16 hi-lo) / v(swizzled)
    gemm_tf32_async<<<dim3(QKV_N / GBN, ROWS / GBM), 256, GEMM_SMEM>>>(
        ROWS, QKV_N, DMODEL, xr, wqkvr, bqkv, nullptr, qs, khl, vv, 1);

    // 2) causal attention -> ctx (tf32-rounded)
    attn_tc_kernel<<<dim3(SEQ / BQ, BH), 256, ATTN_SMEM>>>(qs, khl, vv, ctx);

    // 3) out = ctx @ Wout + bout
    gemm_tf32_async<<<dim3(DMODEL / GBN, ROWS / GBM), 256, GEMM_SMEM>>>(
        ROWS, DMODEL, DMODEL, ctx, woutr, bout, out, nullptr, nullptr, nullptr, 0);
}

// round 13
// speedup vs baseline: 1.1198x; 1.1198x over previous
#include <cuda_runtime.h>
#include <cuda_bf16.h>
#include <cstdint>
#include <cstddef>

// Problem constants
#define BATCH 2
#define SEQ   2048
#define DMODEL 1024
#define NHEADS 16
#define HD    64
#define ROWS  (BATCH*SEQ)          // 4096
#define QKV_N (3*DMODEL)           // 3072
#define BH    (BATCH*NHEADS)       // 32
#define NKTILES (SEQ/64)           // 32
#define VTILE 5120                 // words per V tile (8 ks * 32 lanes * 20)

// Scratch (allocation-free rule: __device__ globals)
__device__ float    g_qs [(size_t)BH * SEQ * HD];       // Q*scale, fp32, head-major
__device__ uint32_t g_khl[(size_t)BH * SEQ * HD];       // K bf16 hi/lo pairs
__device__ float    g_v  [(size_t)BH * NKTILES * VTILE];// V tf32, fragment-swizzled
__device__ float    g_ctx[(size_t)ROWS * DMODEL];       // ctx, tf32-rounded
__device__ float    g_xr [(size_t)ROWS * DMODEL];       // tf32-rounded x
__device__ float    g_wqkvr[(size_t)DMODEL * QKV_N];    // tf32-rounded Wqkv
__device__ float    g_woutr[(size_t)DMODEL * DMODEL];   // tf32-rounded Wout

// ---------------------------------------------------------------------------
// helpers
// ---------------------------------------------------------------------------
__device__ __forceinline__ uint32_t f2tf(float x) {
    uint32_t r;
    asm("cvt.rna.tf32.f32 %0, %1;" : "=r"(r) : "f"(x));
    return r;
}

__device__ __forceinline__ void mma_tf32(float* c, const uint32_t* a, const uint32_t* b) {
    asm volatile(
        "mma.sync.aligned.m16n8k8.row.col.f32.tf32.tf32.f32 "
        "{%0,%1,%2,%3}, {%4,%5,%6,%7}, {%8,%9}, {%0,%1,%2,%3};"
        : "+f"(c[0]), "+f"(c[1]), "+f"(c[2]), "+f"(c[3])
        : "r"(a[0]), "r"(a[1]), "r"(a[2]), "r"(a[3]), "r"(b[0]), "r"(b[1]));
}

__device__ __forceinline__ void mma_bf16(float* c, const uint32_t* a, const uint32_t* b) {
    asm volatile(
        "mma.sync.aligned.m16n8k16.row.col.f32.bf16.bf16.f32 "
        "{%0,%1,%2,%3}, {%4,%5,%6,%7}, {%8,%9}, {%0,%1,%2,%3};"
        : "+f"(c[0]), "+f"(c[1]), "+f"(c[2]), "+f"(c[3])
        : "r"(a[0]), "r"(a[1]), "r"(a[2]), "r"(a[3]), "r"(b[0]), "r"(b[1]));
}

// split (x,y) fp32 pair -> bf16x2 hi word + bf16x2 lo word (lo = residual)
__device__ __forceinline__ void split_bf16x2(float x, float y, uint32_t& h, uint32_t& l) {
    __nv_bfloat16 xh = __float2bfloat16(x);
    __nv_bfloat16 yh = __float2bfloat16(y);
    __nv_bfloat162 hh = __halves2bfloat162(xh, yh);
    __nv_bfloat162 ll = __halves2bfloat162(
        __float2bfloat16(x - __bfloat162float(xh)),
        __float2bfloat16(y - __bfloat162float(yh)));
    h = *(uint32_t*)&hh;
    l = *(uint32_t*)&ll;
}

__device__ __forceinline__ void cpa16(void* smem, const void* gmem) {
    uint32_t sa = (uint32_t)__cvta_generic_to_shared(smem);
    asm volatile("cp.async.cg.shared.global [%0], [%1], 16;" :: "r"(sa), "l"(gmem));
}
#define CP_COMMIT() asm volatile("cp.async.commit_group;")
#define CP_WAIT1()  asm volatile("cp.async.wait_group 1;")

// ---------------------------------------------------------------------------
// prepass: round fp32 -> tf32-rounded fp32
// ---------------------------------------------------------------------------
__global__ void round_tf32_kernel(const float4* __restrict__ src,
                                  float4* __restrict__ dst, int n4)
{
    int i = blockIdx.x * blockDim.x + threadIdx.x;
    if (i < n4) {
        float4 v = src[i];
        v.x = __uint_as_float(f2tf(v.x));
        v.y = __uint_as_float(f2tf(v.y));
        v.z = __uint_as_float(f2tf(v.z));
        v.w = __uint_as_float(f2tf(v.w));
        dst[i] = v;
    }
}

// ---------------------------------------------------------------------------
// tf32 tensor-core GEMM, cp.async 2-stage pipeline (R10-proven mainloop).
// mode 0: C = A@B + bias.  mode 1: QKV scatter epilogue (head-major).
// BM=BN=128, BK=32, 256 threads = 8 warps (4Mx2N), warp tile 32x64.
// ---------------------------------------------------------------------------
#define GBM 128
#define GBN 128
#define GBK 32
#define ASTR 36
#define BSTR 136
#define GEMM_SMEM ((2*GBM*ASTR + 2*GBK*BSTR) * 4)   // 71680 B

__global__ __launch_bounds__(256, 2) void gemm_tf32_async(
    int M, int N, int K,
    const float* __restrict__ A,
    const float* __restrict__ B,
    const float* __restrict__ bias,
    float* __restrict__ C,
    float* __restrict__ qs, uint32_t* __restrict__ khl, float* __restrict__ vv,
    int mode)
{
    extern __shared__ float gsm[];
    float* AsB = gsm;
    float* BsB = gsm + 2 * GBM * ASTR;

    const int tid  = threadIdx.x;
    const int warp = tid >> 5;
    const int lane = tid & 31;
    const int grp  = lane >> 2;
    const int tig  = lane & 3;
    const int wm   = (warp >> 1) * 32;
    const int wn   = (warp & 1) * 64;
    const int bm   = blockIdx.y * GBM;
    const int bn   = blockIdx.x * GBN;

    const float* Abase = A + (size_t)bm * K;
    const float* Bbase = B + bn;

    float acc[2][8][4];
    #pragma unroll
    for (int mi = 0; mi < 2; mi++)
        #pragma unroll
        for (int ni = 0; ni < 8; ni++)
            #pragma unroll
            for (int r = 0; r < 4; r++) acc[mi][ni][r] = 0.f;

    auto loadStage = [&](int s, int k0) {
        float* Ab = AsB + s * (GBM * ASTR);
        float* Bb = BsB + s * (GBK * BSTR);
        #pragma unroll
        for (int u = 0; u < 4; u++) {
            int f = tid + u * 256;
            int r = f >> 3, k4 = (f & 7) * 4;
            cpa16(Ab + r * ASTR + k4, Abase + (size_t)r * K + k0 + k4);
        }
        #pragma unroll
        for (int u = 0; u < 4; u++) {
            int f = tid + u * 256;
            int r = f >> 5, c4 = (f & 31) * 4;
            cpa16(Bb + r * BSTR + c4, Bbase + (size_t)(k0 + r) * N + c4);
        }
    };

    loadStage(0, 0); CP_COMMIT();
    loadStage(1, GBK); CP_COMMIT();
    CP_WAIT1();
    __syncthreads();

    int cur = 0;
    for (int k0 = 0; k0 < K; k0 += GBK) {
        const float* Ab = AsB + cur * (GBM * ASTR);
        const float* Bb = BsB + cur * (GBK * BSTR);

        #pragma unroll
        for (int ks = 0; ks < 4; ks++) {
            const int kb = ks * 8;
            uint32_t a[2][4], b[8][2];
            #pragma unroll
            for (int mi = 0; mi < 2; mi++) {
                int r0 = wm + mi * 16 + grp;
                a[mi][0] = __float_as_uint(Ab[(size_t)r0 * ASTR + kb + tig]);
                a[mi][1] = __float_as_uint(Ab[(size_t)(r0 + 8) * ASTR + kb + tig]);
                a[mi][2] = __float_as_uint(Ab[(size_t)r0 * ASTR + kb + tig + 4]);
                a[mi][3] = __float_as_uint(Ab[(size_t)(r0 + 8) * ASTR + kb + tig + 4]);
            }
            #pragma unroll
            for (int ni = 0; ni < 8; ni++) {
                int c0 = wn + ni * 8 + grp;
                b[ni][0] = __float_as_uint(Bb[(size_t)(kb + tig) * BSTR + c0]);
                b[ni][1] = __float_as_uint(Bb[(size_t)(kb + tig + 4) * BSTR + c0]);
            }
            #pragma unroll
            for (int mi = 0; mi < 2; mi++)
                #pragma unroll
                for (int ni = 0; ni < 8; ni++)
                    mma_tf32(acc[mi][ni], a[mi], b[ni]);
        }

        __syncthreads();
        int knext = k0 + 2 * GBK;
        if (knext < K) loadStage(cur, knext);
        CP_COMMIT();
        CP_WAIT1();
        __syncthreads();
        cur ^= 1;
    }

    if (mode == 0) {
        #pragma unroll
        for (int mi = 0; mi < 2; mi++) {
            #pragma unroll
            for (int ni = 0; ni < 8; ni++) {
                int row0 = bm + wm + mi * 16 + grp;
                int col  = bn + wn + ni * 8 + tig * 2;
                float2 bv = *(const float2*)(bias + col);
                float2 o0, o1;
                o0.x = acc[mi][ni][0] + bv.x;
                o0.y = acc[mi][ni][1] + bv.y;
                o1.x = acc[mi][ni][2] + bv.x;
                o1.y = acc[mi][ni][3] + bv.y;
                *(float2*)(C + (size_t)row0 * N + col)       = o0;
                *(float2*)(C + (size_t)(row0 + 8) * N + col) = o1;
            }
        }
    } else {
        // QKV scatter: Q scaled fp32 head-major; K bf16 hi/lo pairs head-major;
        // V tf32 in mma-fragment-swizzled tiles.
        auto scatter = [&](int row, int col, float va, float vb) {
            int b2 = row >> 11, s = row & 2047;
            int sec = col >> 10;
            int h = (col & 1023) >> 6, d = col & 63;
            if (sec == 0) {
                size_t base = ((size_t)((b2 << 4) + h) * SEQ + s) * HD + d;
                float2 o = { va * 0.125f, vb * 0.125f };
                *(float2*)(qs + base) = o;
            } else if (sec == 1) {
                size_t base = ((size_t)((b2 << 4) + h) * SEQ + s) * HD + d;
                uint2 o;
                split_bf16x2(va, vb, o.x, o.y);
                *(uint2*)(khl + base) = o;
            } else {
                int ktile = s >> 6, j = s & 63;
                int ksv = j >> 3, tigv = j & 3, rv = (j >> 2) & 1;
                size_t tbase = ((size_t)((b2 << 4) + h) * NKTILES + ktile) * VTILE;
                int g0 = d & 7, nt0 = d >> 3;
                int g1 = (d + 1) & 7, nt1 = (d + 1) >> 3;
                vv[tbase + (size_t)(ksv * 32 + 4 * g0 + tigv) * 20 + nt0 * 2 + rv] =
                    __uint_as_float(f2tf(va));
                vv[tbase + (size_t)(ksv * 32 + 4 * g1 + tigv) * 20 + nt1 * 2 + rv] =
                    __uint_as_float(f2tf(vb));
            }
        };
        #pragma unroll
        for (int mi = 0; mi < 2; mi++) {
            #pragma unroll
            for (int ni = 0; ni < 8; ni++) {
                int row0 = bm + wm + mi * 16 + grp;
                int col  = bn + wn + ni * 8 + tig * 2;
                float2 bv = *(const float2*)(bias + col);
                scatter(row0,     col, acc[mi][ni][0] + bv.x, acc[mi][ni][1] + bv.y);
                scatter(row0 + 8, col, acc[mi][ni][2] + bv.x, acc[mi][ni][3] + bv.y);
            }
        }
    }
}

// ---------------------------------------------------------------------------
// Tensor-core causal flash attention, cp.async 2-stage K/V pipeline.
// QK^T: 3xBF16 m16n8k16 (hi/lo split).  PV: 1xTF32, V pre-swizzled so each
// thread's B-fragments for one ks come from 4 LDS.128 (conflict-free, stride 20).
// Block = 128 q rows of one (b,h); 8 warps; 2 CTAs/SM.
// ---------------------------------------------------------------------------
#define BQ 128
#define BK 64
#define KROW 72     // uint32 words per K smem row (64 data + 8 pad)
#define PSTR 68
#define KTILE (BK*KROW)
#define ATTN_SMEM ((2*KTILE + 2*VTILE + BQ*PSTR) * 4)   // 112640 B

__global__ __launch_bounds__(256, 2) void attn_tc_kernel(
    const float* __restrict__ qs, const uint32_t* __restrict__ khl,
    const float* __restrict__ vsrc, float* __restrict__ ctx)
{
    extern __shared__ float sm[];
    uint32_t* KhlS = (uint32_t*)sm;         // [2][BK][KROW]
    float* VtS = sm + 2 * KTILE;            // [2][VTILE] fragment-swizzled
    float* Ps  = VtS + 2 * VTILE;           // [BQ][PSTR]

    const int qt = gridDim.x - 1 - blockIdx.x;   // heavy tiles first
    const int bh = blockIdx.y;
    const int b = bh >> 4;
    const int tid = threadIdx.x;
    const int w = tid >> 5, lane = tid & 31;
    const int grp = lane >> 2, tig = lane & 3;

    const uint32_t* kbase = khl + (size_t)bh * SEQ * HD;
    const float* vbase = vsrc + (size_t)bh * NKTILES * VTILE;

    auto load_tile = [&](int kt, int stage) {
        const uint32_t* ks = kbase + (size_t)(kt * BK) * HD;
        uint32_t* kd = KhlS + stage * KTILE;
        #pragma unroll
        for (int u = 0; u < 4; u++) {
            int f = tid + u * 256;
            int j = f >> 4, c = (f & 15) * 4;
            cpa16(kd + j * KROW + c, ks + (size_t)j * HD + c);
        }
        const float* vs = vbase + (size_t)kt * VTILE;
        float* vd = VtS + stage * VTILE;
        #pragma unroll
        for (int u = 0; u < 5; u++) {
            int f = (tid + u * 256) * 4;    // 1280 x 16B = 5120 words
            cpa16(vd + f, vs + f);
        }
    };

    const int nkt = 2 * qt + 2;

    load_tile(0, 0); CP_COMMIT();
    load_tile(1, 1); CP_COMMIT();

    const float* qsrc = qs + ((size_t)bh * SEQ + qt * BQ) * HD;
    #pragma unroll
    for (int u = 0; u < 8; u++) {
        int f = tid + u * 256;
        int r = f >> 4, c = (f & 15) * 4;
        *(float4*)(Ps + r * PSTR + c) = *(const float4*)(qsrc + (size_t)r * HD + c);
    }
    __syncthreads();

    const int r0 = w * 16 + grp, r1 = r0 + 8;

    // Q fragments: bf16 hi/lo split, m16n8k16 layout, register resident
    uint32_t qh[4][4], ql[4][4];
    #pragma unroll
    for (int ks = 0; ks < 4; ks++) {
        int kb = ks * 16 + 2 * tig;
        float2 x0 = *(const float2*)(Ps + r0 * PSTR + kb);
        float2 x1 = *(const float2*)(Ps + r1 * PSTR + kb);
        float2 x2 = *(const float2*)(Ps + r0 * PSTR + kb + 8);
        float2 x3 = *(const float2*)(Ps + r1 * PSTR + kb + 8);
        split_bf16x2(x0.x, x0.y, qh[ks][0], ql[ks][0]);
        split_bf16x2(x1.x, x1.y, qh[ks][1], ql[ks][1]);
        split_bf16x2(x2.x, x2.y, qh[ks][2], ql[ks][2]);
        split_bf16x2(x3.x, x3.y, qh[ks][3], ql[ks][3]);
    }

    float oacc[8][4];
    #pragma unroll
    for (int nt = 0; nt < 8; nt++)
        #pragma unroll
        for (int r = 0; r < 4; r++) oacc[nt][r] = 0.f;
    float m0 = -1e30f, m1 = -1e30f, l0 = 0.f, l1 = 0.f;

    int cur = 0;
    for (int kt = 0; kt < nkt; kt++) {
        CP_WAIT1();
        __syncthreads();

        const bool active = (kt * BK <= qt * BQ + w * 16 + 15);
        if (active) {
            const uint32_t* Khl = KhlS + cur * KTILE;
            const float* Vt = VtS + cur * VTILE;

            // --- QK^T (3xBF16, m16n8k16) ---
            float s[8][4];
            #pragma unroll
            for (int nt = 0; nt < 8; nt++)
                #pragma unroll
                for (int r = 0; r < 4; r++) s[nt][r] = 0.f;

            #pragma unroll
            for (int ks = 0; ks < 4; ks++) {
                #pragma unroll
                for (int nt = 0; nt < 8; nt++) {
                    int bi = (nt * 8 + grp) * KROW + (ks * 8 + tig) * 2;
                    uint2 w0 = *(const uint2*)&Khl[bi];
                    uint2 w1 = *(const uint2*)&Khl[bi + 8];
                    uint32_t bh2[2] = { w0.x, w1.x };
                    uint32_t bl2[2] = { w0.y, w1.y };
                    mma_bf16(s[nt], qh[ks], bh2);
                    mma_bf16(s[nt], qh[ks], bl2);
                    mma_bf16(s[nt], ql[ks], bh2);
                }
            }

            // --- causal mask (diagonal tiles only) ---
            const int q0 = qt * BQ + r0, q1 = qt * BQ + r1;
            if (kt * BK + BK - 1 > q0) {
                #pragma unroll
                for (int nt = 0; nt < 8; nt++) {
                    int jg = kt * BK + nt * 8 + 2 * tig;
                    if (jg     > q0) s[nt][0] = -1e30f;
                    if (jg + 1 > q0) s[nt][1] = -1e30f;
                    if (jg     > q1) s[nt][2] = -1e30f;
                    if (jg + 1 > q1) s[nt][3] = -1e30f;
                }
            }

            // --- online softmax ---
            float tm0 = -1e30f, tm1 = -1e30f;
            #pragma unroll
            for (int nt = 0; nt < 8; nt++) {
                tm0 = fmaxf(tm0, fmaxf(s[nt][0], s[nt][1]));
                tm1 = fmaxf(tm1, fmaxf(s[nt][2], s[nt][3]));
            }
            tm0 = fmaxf(tm0, __shfl_xor_sync(0xffffffffu, tm0, 1));
            tm0 = fmaxf(tm0, __shfl_xor_sync(0xffffffffu, tm0, 2));
            tm1 = fmaxf(tm1, __shfl_xor_sync(0xffffffffu, tm1, 1));
            tm1 = fmaxf(tm1, __shfl_xor_sync(0xffffffffu, tm1, 2));
            float nm0 = fmaxf(m0, tm0), nm1 = fmaxf(m1, tm1);
            float cr0 = __expf(m0 - nm0), cr1 = __expf(m1 - nm1);
            m0 = nm0; m1 = nm1;
            l0 *= cr0; l1 *= cr1;
            #pragma unroll
            for (int nt = 0; nt < 8; nt++) {
                oacc[nt][0] *= cr0; oacc[nt][1] *= cr0;
                oacc[nt][2] *= cr1; oacc[nt][3] *= cr1;
            }

            float ls0 = 0.f, ls1 = 0.f;
            #pragma unroll
            for (int nt = 0; nt < 8; nt++) {
                float p0 = __expf(s[nt][0] - m0);
                float p1 = __expf(s[nt][1] - m0);
                float p2 = __expf(s[nt][2] - m1);
                float p3 = __expf(s[nt][3] - m1);
                ls0 += p0 + p1; ls1 += p2 + p3;
                int cc = nt * 8 + 2 * tig;
                float2 w0, w1;
                w0.x = __uint_as_float(f2tf(p0)); w0.y = __uint_as_float(f2tf(p1));
                w1.x = __uint_as_float(f2tf(p2)); w1.y = __uint_as_float(f2tf(p3));
                *(float2*)(Ps + r0 * PSTR + cc) = w0;
                *(float2*)(Ps + r1 * PSTR + cc) = w1;
            }
            ls0 += __shfl_xor_sync(0xffffffffu, ls0, 1);
            ls0 += __shfl_xor_sync(0xffffffffu, ls0, 2);
            ls1 += __shfl_xor_sync(0xffffffffu, ls1, 1);
            ls1 += __shfl_xor_sync(0xffffffffu, ls1, 2);
            l0 += ls0; l1 += ls1;

            __syncwarp();   // P stores visible to same-warp fragment loads

            // --- PV (1xTF32, m16n8k8), V fragment-swizzled: 4x LDS.128 per ks ---
            #pragma unroll
            for (int ks = 0; ks < 8; ks++) {
                uint32_t a[4];
                int c0i = ks * 8 + tig;
                a[0] = __float_as_uint(Ps[r0 * PSTR + c0i]);
                a[1] = __float_as_uint(Ps[r1 * PSTR + c0i]);
                a[2] = __float_as_uint(Ps[r0 * PSTR + c0i + 4]);
                a[3] = __float_as_uint(Ps[r1 * PSTR + c0i + 4]);
                const float* vc = Vt + (ks * 32 + lane) * 20;
                float4 vq[4];                      // contiguous array
                vq[0] = *(const float4*)(vc);
                vq[1] = *(const float4*)(vc + 4);
                vq[2] = *(const float4*)(vc + 8);
                vq[3] = *(const float4*)(vc + 12);
                const float* vw = (const float*)vq;   // 16 contiguous floats
                #pragma unroll
                for (int nt = 0; nt < 8; nt++) {
                    uint32_t bb[2];
                    bb[0] = __float_as_uint(vw[nt * 2]);
                    bb[1] = __float_as_uint(vw[nt * 2 + 1]);
                    mma_tf32(oacc[nt], a, bb);
                }
            }
        }

        __syncthreads();
        if (kt + 2 < nkt) load_tile(kt + 2, cur);
        CP_COMMIT();
        cur ^= 1;
    }

    // --- epilogue: write tf32-rounded ctx (out-proj consumes it as A) ---
    float inv0 = 1.f / l0, inv1 = 1.f / l1;
    const int h = bh & 15;
    float* ob = ctx + (size_t)(b * SEQ + qt * BQ) * DMODEL + h * HD;
    #pragma unroll
    for (int nt = 0; nt < 8; nt++) {
        int cc = nt * 8 + 2 * tig;
        float2 o0, o1;
        o0.x = __uint_as_float(f2tf(oacc[nt][0] * inv0));
        o0.y = __uint_as_float(f2tf(oacc[nt][1] * inv0));
        o1.x = __uint_as_float(f2tf(oacc[nt][2] * inv1));
        o1.y = __uint_as_float(f2tf(oacc[nt][3] * inv1));
        *(float2*)(ob + (size_t)r0 * DMODEL + cc) = o0;
        *(float2*)(ob + (size_t)r1 * DMODEL + cc) = o1;
    }
}

// ---------------------------------------------------------------------------
extern "C" void kernel_launch(void* const* d_in, const int* in_sizes, int n_in,
                              void* d_out, int out_size)
{
    const float* x    = (const float*)d_in[0];
    const float* Wqkv = (const float*)d_in[1];
    const float* bqkv = (const float*)d_in[2];
    const float* Wout = (const float*)d_in[3];
    const float* bout = (const float*)d_in[4];
    float* out = (float*)d_out;

    float *qs, *vv, *ctx, *xr, *wqkvr, *woutr;
    uint32_t* khl;
    cudaGetSymbolAddress((void**)&qs, g_qs);
    cudaGetSymbolAddress((void**)&khl, g_khl);
    cudaGetSymbolAddress((void**)&vv, g_v);
    cudaGetSymbolAddress((void**)&ctx, g_ctx);
    cudaGetSymbolAddress((void**)&xr, g_xr);
    cudaGetSymbolAddress((void**)&wqkvr, g_wqkvr);
    cudaGetSymbolAddress((void**)&woutr, g_woutr);

    cudaFuncSetAttribute(gemm_tf32_async,
                         cudaFuncAttributeMaxDynamicSharedMemorySize, GEMM_SMEM);
    cudaFuncSetAttribute(attn_tc_kernel,
                         cudaFuncAttributeMaxDynamicSharedMemorySize, ATTN_SMEM);

    // 0) prepass: tf32-round GEMM inputs
    {
        int n4x = ROWS * DMODEL / 4;
        int n4w = DMODEL * QKV_N / 4;
        int n4o = DMODEL * DMODEL / 4;
        round_tf32_kernel<<<(n4x + 255) / 256, 256>>>((const float4*)x, (float4*)xr, n4x);
        round_tf32_kernel<<<(n4w + 255) / 256, 256>>>((const float4*)Wqkv, (float4*)wqkvr, n4w);
        round_tf32_kernel<<<(n4o + 255) / 256, 256>>>((const float4*)Wout, (float4*)woutr, n4o);
    }

    // 1) qkv projection with scatter epilogue -> qs / khl(bf16 hi-lo) / v(swizzled)
    gemm_tf32_async<<<dim3(QKV_N / GBN, ROWS / GBM), 256, GEMM_SMEM>>>(
        ROWS, QKV_N, DMODEL, xr, wqkvr, bqkv, nullptr, qs, khl, vv, 1);

    // 2) causal attention -> ctx (tf32-rounded)
    attn_tc_kernel<<<dim3(SEQ / BQ, BH), 256, ATTN_SMEM>>>(qs, khl, vv, ctx);

    // 3) out = ctx @ Wout + bout
    gemm_tf32_async<<<dim3(DMODEL / GBN, ROWS / GBM), 256, GEMM_SMEM>>>(
        ROWS, DMODEL, DMODEL, ctx, woutr, bout, out, nullptr, nullptr, nullptr, 0);
}